// round 17
// baseline (speedup 1.0000x reference)
#include <cuda_runtime.h>
#include <cuda_bf16.h>
#include <math.h>

#define NV    6144
#define HV    4
#define EPSV  1e-7f
#define MINV  1e-15f
#define NSEG  32
#define SEGR  192
#define CAP   24
#define AST   68
#define WLN   320

// ---------------- scratch ----------------
__device__ int   g_cnt[NV * NSEG];
__device__ int   g_nbr[(size_t)NV * NSEG * CAP];
__device__ float g_att[(size_t)HV * NV * AST];  // [0..63] raw att ov; [64..67]=t_att,sh_att,t_dat,sh_dat
__device__ float g_dat[(size_t)HV * NV * AST];  // [0..63] raw dat ov
__device__ float g_osqF[16 * NV];               // k_feat partial osq [osel*8+m][node]
__device__ float g_u  [(size_t)HV * NV * 64];   // node-major mobius logmap vectors
__device__ float g_pcT[(size_t)256 * NV];       // feature-major RAW Wo outputs
__device__ float g_osqP[16 * NV];               // k_post1 partial osq [osel*4+h][node]
__device__ float g_as [HV * NV];                // fused per-(head,node) scale
__device__ float g_WlP[256 * WLN];              // W_lin^T padded (zeros beyond 260)

// ---------------- helpers ----------------
__device__ __forceinline__ float wred(float v) {
#pragma unroll
    for (int o = 16; o; o >>= 1) v += __shfl_xor_sync(0xffffffffu, v, o);
    return v;
}
__device__ __forceinline__ float acoshr(float z) {          // precise (node-level uses)
    float t = fmaxf(z * z - 1.0f, 0.0f);
    return logf(z + sqrtf(t));
}
__device__ __forceinline__ float acoshf_fast(float z) {     // fast (per-edge hot path)
    float t = fmaxf(z * z - 1.0f, 0.0f);
    return __logf(z + sqrtf(t));
}

// ---------------- K1: neighbor lists + W_lin transpose ----------------
__global__ __launch_bounds__(256) void k_build(const float* __restrict__ adj,
                                               const float* __restrict__ Wl) {
    if (blockIdx.y == NSEG) {
        for (int e = blockIdx.x * 256 + threadIdx.x; e < 256 * 260; e += 24 * 256) {
            int kk = e / 260, n = e % 260;
            g_WlP[(size_t)kk * WLN + n] = Wl[n * 257 + kk + 1];
        }
        return;
    }
    int c   = blockIdx.x * 256 + threadIdx.x;
    int seg = blockIdx.y;
    int cnt = 0;
    size_t base = ((size_t)c * NSEG + seg) * CAP;
    int j0 = seg * SEGR;
    for (int r = 0; r < SEGR; r += 8) {
        float v[8];
#pragma unroll
        for (int u = 0; u < 8; u++) v[u] = adj[(size_t)(j0 + r + u) * NV + c];
#pragma unroll
        for (int u = 0; u < 8; u++) {
            if (v[u] > 0.01f) {
                if (cnt < CAP) g_nbr[base + cnt] = j0 + r + u;
                cnt++;
            }
        }
    }
    g_cnt[c * NSEG + seg] = (cnt < CAP) ? cnt : CAP;
}

// ---------------- K2: hyp_linear att/data -> RAW half-rows + partial osq ------
#define SMEM_FEAT ((8320 + 2048) * 4)

__global__ __launch_bounds__(128) void k_feat(const float* __restrict__ x,
                                              const float* __restrict__ Wa,
                                              const float* __restrict__ Wd) {
    extern __shared__ float sm[];
    float*  su  = sm;                 // 128*65
    float*  sW  = sm + 8320;          // 32*64
    float4* sW4 = (float4*)sW;
    int t = threadIdx.x;
    int m = blockIdx.y, h = m & 3, osel = blockIdx.z;
    const float* W = (m < 4) ? (Wa + h * 4225) : (Wd + h * 4225);
    int nb = blockIdx.x * 128;

    for (int e = t; e < 128 * 65; e += 128) su[e] = x[(size_t)nb * 65 + e];
    for (int e = t; e < 32 * 64; e += 128) {
        int oo = e >> 6, c = e & 63;
        sW[e] = W[(osel * 32 + oo + 1) * 65 + 1 + c];
    }
    __syncthreads();

    float u[64];
    float x0 = su[t * 65];
    float q0 = 0.f, q1 = 0.f, q2 = 0.f, q3 = 0.f;
#pragma unroll
    for (int c = 0; c < 64; c += 4) {
        float a = su[t * 65 + 1 + c], b = su[t * 65 + 2 + c];
        float cc = su[t * 65 + 3 + c], d = su[t * 65 + 4 + c];
        u[c] = a; u[c + 1] = b; u[c + 2] = cc; u[c + 3] = d;
        q0 += a * a; q1 += b * b; q2 += cc * cc; q3 += d * d;
    }
    float nsq = (q0 + q1) + (q2 + q3);
    float scale = acoshr(fmaxf(x0, 1.0f + EPSV)) / fmaxf(sqrtf(nsq), MINV);
#pragma unroll
    for (int c = 0; c < 64; c++) u[c] *= scale;

    float* dst = (m < 4) ? g_att : g_dat;
    float* R = dst + ((size_t)(h * NV) + nb + t) * AST + osel * 32;
    float osq = 0.f;
#pragma unroll 2
    for (int o4 = 0; o4 < 8; o4++) {
        float4 ov4;
        float* po = (float*)&ov4;
#pragma unroll
        for (int jj = 0; jj < 4; jj++) {
            int oo = o4 * 4 + jj;
            float a0 = 0.f, a1 = 0.f, a2 = 0.f, a3 = 0.f;
#pragma unroll
            for (int c4 = 0; c4 < 16; c4++) {
                float4 wv = sW4[oo * 16 + c4];
                a0 += wv.x * u[4 * c4];
                a1 += wv.y * u[4 * c4 + 1];
                a2 += wv.z * u[4 * c4 + 2];
                a3 += wv.w * u[4 * c4 + 3];
            }
            float ov = (a0 + a1) + (a2 + a3);
            po[jj] = ov;
            osq += ov * ov;
        }
        *(float4*)&R[o4 * 4] = ov4;
    }
    g_osqF[(osel * 8 + m) * NV + nb + t] = osq;
}

// ---------------- K2b: combine osq -> t/sh extras in g_att rows --------------
__global__ __launch_bounds__(256) void k_ts(void) {
    int node = blockIdx.x * 256 + threadIdx.x;
    int m = blockIdx.y, h = m & 3;
    float osq = g_osqF[m * NV + node] + g_osqF[(8 + m) * NV + node];
    float n2 = fmaxf(sqrtf(osq), MINV);
    float shv = sinhf(n2) / n2;
    float tv = sqrtf(1.0f + shv * shv * osq);
    float* R = g_att + ((size_t)(h * NV) + node) * AST + ((m < 4) ? 64 : 66);
    R[0] = tv;
    R[1] = shv;
}

// ---------------- K3: sparse attention + mobius (best-measured form) ---------
__global__ __launch_bounds__(128) void k_attn(void) {
    int i = blockIdx.x;
    int w = threadIdx.x >> 5, l = threadIdx.x & 31;
    int h = w;
    int s = l & 3, g = l >> 2;      // feature quarter, neighbor slot (0..7)
    __shared__ int slist[808];
    __shared__ int stot;

    if (threadIdx.x < 32) {
        int c = g_cnt[i * NSEG + l];
        int sc = c;
#pragma unroll
        for (int o = 1; o < 32; o <<= 1) {
            int v = __shfl_up_sync(0xffffffffu, sc, o);
            if (l >= o) sc += v;
        }
        int off = sc - c;
        const int* lst = g_nbr + ((size_t)i * NSEG + l) * CAP;
        for (int k = 0; k < c; k++) slist[off + k] = lst[k];
        if (l == 31) stot = sc;
    }
    __syncthreads();
    int nk = stot;
    int nk8 = (nk + 7) & ~7;
    if (threadIdx.x < nk8 - nk) slist[nk + threadIdx.x] = slist[0];
    __syncthreads();

    const float* Ai = g_att + ((size_t)(h * NV) + i) * AST;
    float4 ei = *(const float4*)(Ai + 64);   // t_att, sh_att, t_dat, sh_dat
    float ai0 = ei.x, shA_i = ei.y;
    float4 a0 = *(const float4*)(Ai + 16 * s);
    float4 a1 = *(const float4*)(Ai + 16 * s + 4);
    float4 a2 = *(const float4*)(Ai + 16 * s + 8);
    float4 a3 = *(const float4*)(Ai + 16 * s + 12);
    a0.x *= shA_i; a0.y *= shA_i; a0.z *= shA_i; a0.w *= shA_i;
    a1.x *= shA_i; a1.y *= shA_i; a1.z *= shA_i; a1.w *= shA_i;
    a2.x *= shA_i; a2.y *= shA_i; a2.z *= shA_i; a2.w *= shA_i;
    a3.x *= shA_i; a3.y *= shA_i; a3.z *= shA_i; a3.w *= shA_i;

    float T1 = 0.f, T2 = 0.f, Up = 0.f, Qp = 0.f;
    for (int kc = 0; kc < nk8; kc += 8) {
        int j = slist[kc + g];
        const float* Aj = g_att + ((size_t)(h * NV) + j) * AST;

        float d1[8], d2[8];
#pragma unroll
        for (int gg = 0; gg < 8; gg++) {
            int jg = slist[kc + gg];
            const float* Dj = g_dat + ((size_t)(h * NV) + jg) * AST;
            d1[gg] = Dj[l];
            d2[gg] = Dj[l + 32];
        }

        float4 b0 = *(const float4*)(Aj + 16 * s);
        float4 b1 = *(const float4*)(Aj + 16 * s + 4);
        float4 b2 = *(const float4*)(Aj + 16 * s + 8);
        float4 b3 = *(const float4*)(Aj + 16 * s + 12);
        float4 ej = *(const float4*)(Aj + 64);
        float part = a0.x * b0.x + a0.y * b0.y + a0.z * b0.z + a0.w * b0.w
                   + a1.x * b1.x + a1.y * b1.y + a1.z * b1.z + a1.w * b1.w
                   + a2.x * b2.x + a2.y * b2.y + a2.z * b2.z + a2.w * b2.w
                   + a3.x * b3.x + a3.y * b3.y + a3.z * b3.z + a3.w * b3.w;
        part += __shfl_xor_sync(0xffffffffu, part, 1);
        part += __shfl_xor_sync(0xffffffffu, part, 2);
        float th = fmaxf(ai0 * ej.x - ej.y * part, 1.0f + EPSV);
        float ar = acoshf_fast(th);
        float S = fminf(ar * ar, 50.0f);
        if (kc + g >= nk) S = 0.0f;
        Up += S * ej.z;
        Qp += S * S;
        float Sgs = S * ej.w;
#pragma unroll
        for (int gg = 0; gg < 8; gg++) {
            float Sg = __shfl_sync(0xffffffffu, Sgs, gg * 4);
            T1 += Sg * d1[gg];
            T2 += Sg * d2[gg];
        }
    }
    float U = wred(Up) * 0.25f;
    float Q = wred(Qp) * 0.25f;

    float nrm = fmaxf(sqrtf(Q), 1e-12f);
    float den = fmaxf(U / nrm, MINV);
    float v1 = (-T1 / nrm) / den, v2 = (-T2 / nrm) / den;
    float nvsq = wred(v1 * v1 + v2 * v2);
    float nv = fmaxf(sqrtf(nvsq), MINV);
    float ncl = fminf(nv, 1.0f - EPSV);
    float f = ncl / ((1.0f + sqrtf(fmaxf(1.0f - ncl * ncl, 0.0f))) * nv);
    float m1 = f * v1, m2 = f * v2;
    float s2 = f * f * nvsq;
    float dd = fmaxf(1.0f - s2, MINV);
    float hb0 = (1.0f + s2) / dd;
    float nyy = fmaxf(2.0f * sqrtf(s2) / dd, MINV);
    float sc2 = acoshr(fmaxf(hb0, 1.0f + EPSV)) * (2.0f / dd) / nyy;
    float* Uo = g_u + ((size_t)(h * NV) + i) * 64;
    Uo[l]      = sc2 * m1;
    Uo[l + 32] = sc2 * m2;
}

// ---------------- K4: Wo matvec, node-per-thread, 4-way o-split --------------
__global__ __launch_bounds__(128) void k_post1(const float* __restrict__ Wo) {
    __shared__ float sW[16 * 64];
    float4* sW4 = (float4*)sW;
    int t = threadIdx.x;
    int h = blockIdx.y, osel = blockIdx.z;
    int node = blockIdx.x * 128 + t;

    for (int e = t; e < 16 * 64; e += 128) {
        int o2 = e >> 6, c = e & 63;
        sW[e] = Wo[h * 4225 + (osel * 16 + o2 + 1) * 65 + 1 + c];
    }
    __syncthreads();

    float u[64];
    const float4* U4 = (const float4*)(g_u + ((size_t)(h * NV) + node) * 64);
#pragma unroll
    for (int c4 = 0; c4 < 16; c4++) {
        float4 v = U4[c4];
        u[4 * c4] = v.x; u[4 * c4 + 1] = v.y; u[4 * c4 + 2] = v.z; u[4 * c4 + 3] = v.w;
    }

    float osq = 0.f;
#pragma unroll 2
    for (int o2 = 0; o2 < 16; o2++) {
        float a0 = 0.f, a1 = 0.f, a2 = 0.f, a3 = 0.f;
#pragma unroll
        for (int c4 = 0; c4 < 16; c4++) {
            float4 wv = sW4[o2 * 16 + c4];
            a0 += wv.x * u[4 * c4];
            a1 += wv.y * u[4 * c4 + 1];
            a2 += wv.z * u[4 * c4 + 2];
            a3 += wv.w * u[4 * c4 + 3];
        }
        float ov = (a0 + a1) + (a2 + a3);
        g_pcT[(size_t)(h * 64 + osel * 16 + o2) * NV + node] = ov;
        osq += ov * ov;
    }
    g_osqP[(osel * 4 + h) * NV + node] = osq;
}

// ---------------- K5: fused per-(head,node) scale ----------------
__global__ __launch_bounds__(256) void k_scal(void) {
    int node = blockIdx.x * 256 + threadIdx.x;
    float cn[HV];
    float ssum = 0.f;
#pragma unroll
    for (int h = 0; h < HV; h++) {
        float osq = g_osqP[h * NV + node] + g_osqP[(4 + h) * NV + node]
                  + g_osqP[(8 + h) * NV + node] + g_osqP[(12 + h) * NV + node];
        float n2 = fmaxf(sqrtf(osq), MINV);
        float sh = sinhf(n2) / n2;
        float tv = sqrtf(1.0f + sh * sh * osq);
        cn[h] = sh / (tv + 1.0f);
        ssum += cn[h] * cn[h] * osq;
    }
    float dd = fmaxf(1.0f - ssum, MINV);
    float hb0 = (1.0f + ssum) / dd;
    float nyy = fmaxf(2.0f * sqrtf(ssum) / dd, MINV);
    float srow = acoshr(fmaxf(hb0, 1.0f + EPSV)) * (2.0f / dd) / nyy;
#pragma unroll
    for (int h = 0; h < HV; h++) g_as[h * NV + node] = cn[h] * srow;
}

// ---------------- K6: fused SGEMM (32x320 tile) + final expmap/proj ----------
// grid 192, block 256. A from g_pcT (scaled), B = full padded W_lin^T row block.
__global__ __launch_bounds__(256) void k_linf(float* __restrict__ out) {
    __shared__ float As[16][33];
    __shared__ float Bs[16][320];
    __shared__ float sAS[4][32];
    int t = threadIdx.x;
    int i0 = blockIdx.x * 32;
    int tx = t & 15, ty = t >> 4;   // tx: col group, ty: row pair
    float4 acc[2][5];
#pragma unroll
    for (int i = 0; i < 2; i++)
#pragma unroll
        for (int jj = 0; jj < 5; jj++) acc[i][jj] = make_float4(0.f, 0.f, 0.f, 0.f);

    if (t < 128) {
        int h = t >> 5, n = t & 31;
        sAS[h][n] = g_as[h * NV + i0 + n];
    }
    __syncthreads();

    for (int k0 = 0; k0 < 256; k0 += 16) {
        int hh = k0 >> 6;
        __syncthreads();
        if (t < 128) {
            int kk = t >> 3, c8 = t & 7;
            float4 av = *(const float4*)&g_pcT[(size_t)(k0 + kk) * NV + i0 + c8 * 4];
            float4 sv = *(const float4*)&sAS[hh][c8 * 4];
            As[kk][c8 * 4 + 0] = av.x * sv.x;
            As[kk][c8 * 4 + 1] = av.y * sv.y;
            As[kk][c8 * 4 + 2] = av.z * sv.z;
            As[kk][c8 * 4 + 3] = av.w * sv.w;
        }
        for (int e = t; e < 1280; e += 256) {
            int kk = e / 80, c4 = e % 80;
            *(float4*)&Bs[kk][c4 * 4] = *(const float4*)&g_WlP[(size_t)(k0 + kk) * WLN + c4 * 4];
        }
        __syncthreads();
#pragma unroll
        for (int k = 0; k < 16; k++) {
            float a0v = As[k][ty * 2], a1v = As[k][ty * 2 + 1];
#pragma unroll
            for (int jj = 0; jj < 5; jj++) {
                float4 b = *(const float4*)&Bs[k][jj * 64 + tx * 4];
                acc[0][jj].x += a0v * b.x; acc[0][jj].y += a0v * b.y;
                acc[0][jj].z += a0v * b.z; acc[0][jj].w += a0v * b.w;
                acc[1][jj].x += a1v * b.x; acc[1][jj].y += a1v * b.y;
                acc[1][jj].z += a1v * b.z; acc[1][jj].w += a1v * b.w;
            }
        }
    }

    // fused epilogue: expmap0 + hyp_proj per row
#pragma unroll
    for (int i = 0; i < 2; i++) {
        float q = 0.f;
#pragma unroll
        for (int jj = 0; jj < 5; jj++) {
            float4 v = acc[i][jj];
            q += v.x * v.x + v.y * v.y + v.z * v.z + v.w * v.w;
        }
        if (tx == 0) q -= acc[i][0].x * acc[i][0].x;   // exclude dim 0 from norm
#pragma unroll
        for (int msk = 1; msk < 16; msk <<= 1)
            q += __shfl_xor_sync(0xffffffffu, q, msk);
        float n2 = fmaxf(sqrtf(q), MINV);
        float sh = sinhf(n2) / n2;
        float tv = sqrtf(1.0f + sh * sh * q);
        int row = i0 + ty * 2 + i;
#pragma unroll
        for (int jj = 0; jj < 5; jj++) {
            int col = jj * 64 + tx * 4;
            if (col < 260) {
                float4 v = acc[i][jj];
                v.x *= sh; v.y *= sh; v.z *= sh; v.w *= sh;
                if (col == 0) v.x = tv;
                *(float4*)&out[(size_t)row * 260 + col] = v;
            }
        }
    }
}

// ---------------- launch ----------------
extern "C" void kernel_launch(void* const* d_in, const int* in_sizes, int n_in,
                              void* d_out, int out_size) {
    const float* x     = (const float*)d_in[0];
    const float* adj   = (const float*)d_in[1];
    const float* W_att = (const float*)d_in[2];
    const float* W_dat = (const float*)d_in[3];
    const float* W_out = (const float*)d_in[4];
    const float* W_lin = (const float*)d_in[5];
    float* out = (float*)d_out;

    cudaFuncSetAttribute(k_feat, cudaFuncAttributeMaxDynamicSharedMemorySize, SMEM_FEAT);

    k_build<<<dim3(NV / 256, NSEG + 1), 256>>>(adj, W_lin);
    k_feat<<<dim3(NV / 128, 8, 2), 128, SMEM_FEAT>>>(x, W_att, W_dat);
    k_ts<<<dim3(NV / 256, 8), 256>>>();
    k_attn<<<NV, 128>>>();
    k_post1<<<dim3(NV / 128, HV, 4), 128>>>(W_out);
    k_scal<<<NV / 256, 256>>>();
    k_linf<<<NV / 32, 256>>>(out);
}